// round 5
// baseline (speedup 1.0000x reference)
#include <cuda_runtime.h>
#include <cuda_bf16.h>
#include <math.h>
#include <stdint.h>

// ---------------------------------------------------------------------------
// GAT layer, N=8192, Fin=Fout=256.
//   h  = X @ W                         [N,256] fp32
//   s1 = h @ a[:256], s2 = h @ a[256:] [N]
//   e_ij = LeakyReLU(s1_i + s2_j), masked by adj, row softmax, out = ELU(P @ h)
// Trick: m_i = LR(s1_i + max(s2)) is a valid softmax shift (LR monotone),
// so adj is read exactly once in the fused kernel.
// ---------------------------------------------------------------------------

#define N_NODES 8192
#define FDIM    256
#define ALPHA   0.2f

// scratch (device globals -- no allocation allowed)
__device__ float g_h[N_NODES * FDIM];     // 8 MB
__device__ float g_s1[N_NODES];
__device__ float g_s2[N_NODES];
__device__ float g_s2max;

// ---------------------------------------------------------------------------
// K1: h = X @ W   (8192x256 @ 256x256), classic SMEM-tiled SIMT GEMM
// ---------------------------------------------------------------------------
#define BM 64
#define BN 64
#define BK 16

__global__ void __launch_bounds__(256) gemm_xw(const float* __restrict__ X,
                                               const float* __restrict__ W) {
    __shared__ float As[BK][BM + 4];   // transposed: As[k][m]
    __shared__ float Bs[BK][BN + 4];
    int tid = threadIdx.x;
    int m0 = blockIdx.y * BM;
    int n0 = blockIdx.x * BN;
    int tx = tid & 15, ty = tid >> 4;

    float acc[4][4];
#pragma unroll
    for (int i = 0; i < 4; i++)
#pragma unroll
        for (int j = 0; j < 4; j++) acc[i][j] = 0.f;

    for (int kt = 0; kt < FDIM; kt += BK) {
        {   // A tile: 64 rows x 16 k
            int r = tid >> 2, k4 = (tid & 3) * 4;
            float4 v = *(const float4*)(X + (size_t)(m0 + r) * FDIM + kt + k4);
            As[k4 + 0][r] = v.x; As[k4 + 1][r] = v.y;
            As[k4 + 2][r] = v.z; As[k4 + 3][r] = v.w;
        }
        {   // B tile: 16 k x 64 cols
            int r = tid >> 4, c4 = (tid & 15) * 4;
            *(float4*)&Bs[r][c4] = *(const float4*)(W + (size_t)(kt + r) * FDIM + n0 + c4);
        }
        __syncthreads();
#pragma unroll
        for (int k = 0; k < BK; k++) {
            float4 a4 = *(const float4*)&As[k][ty * 4];
            float4 b4 = *(const float4*)&Bs[k][tx * 4];
            float a[4] = {a4.x, a4.y, a4.z, a4.w};
            float b[4] = {b4.x, b4.y, b4.z, b4.w};
#pragma unroll
            for (int i = 0; i < 4; i++)
#pragma unroll
                for (int j = 0; j < 4; j++) acc[i][j] = fmaf(a[i], b[j], acc[i][j]);
        }
        __syncthreads();
    }
#pragma unroll
    for (int i = 0; i < 4; i++)
#pragma unroll
        for (int j = 0; j < 4; j++)
            g_h[(size_t)(m0 + ty * 4 + i) * FDIM + n0 + tx * 4 + j] = acc[i][j];
}

// ---------------------------------------------------------------------------
// K2: s1_i = h_i . a[:256], s2_i = h_i . a[256:]   (one warp per row)
// ---------------------------------------------------------------------------
__global__ void __launch_bounds__(256) compute_s(const float* __restrict__ a) {
    int warp = threadIdx.x >> 5;
    int lane = threadIdx.x & 31;
    int row = blockIdx.x * 8 + warp;
    const float* hr = g_h + (size_t)row * FDIM;
    float d1 = 0.f, d2 = 0.f;
#pragma unroll
    for (int q = 0; q < 2; q++) {
        int c = lane * 4 + q * 128;
        float4 h4 = *(const float4*)(hr + c);
        float4 a1 = *(const float4*)(a + c);
        float4 a2 = *(const float4*)(a + FDIM + c);
        d1 += h4.x * a1.x + h4.y * a1.y + h4.z * a1.z + h4.w * a1.w;
        d2 += h4.x * a2.x + h4.y * a2.y + h4.z * a2.z + h4.w * a2.w;
    }
#pragma unroll
    for (int off = 16; off > 0; off >>= 1) {
        d1 += __shfl_xor_sync(0xFFFFFFFFu, d1, off);
        d2 += __shfl_xor_sync(0xFFFFFFFFu, d2, off);
    }
    if (lane == 0) { g_s1[row] = d1; g_s2[row] = d2; }
}

// ---------------------------------------------------------------------------
// K3: global max of s2 (single block)
// ---------------------------------------------------------------------------
__global__ void __launch_bounds__(1024) s2max_kernel() {
    __shared__ float sm[1024];
    float m = -INFINITY;
    for (int i = threadIdx.x; i < N_NODES; i += 1024) m = fmaxf(m, g_s2[i]);
    sm[threadIdx.x] = m;
    __syncthreads();
    for (int s = 512; s > 0; s >>= 1) {
        if (threadIdx.x < s) sm[threadIdx.x] = fmaxf(sm[threadIdx.x], sm[threadIdx.x + s]);
        __syncthreads();
    }
    if (threadIdx.x == 0) g_s2max = sm[0];
}

// ---------------------------------------------------------------------------
// K4: fused masked-softmax @ h with tf32 mma.sync, then ELU
//   CTA: 128 rows (i) x 256 features (f), loop over j in chunks of 64.
//   512 threads = 16 warps in a 4x4 grid; each warp: 32 rows x 64 cols
//   = 2 m16 tiles x 8 n8 tiles of m16n8k8 tf32 mma (fp32 accum).
// ---------------------------------------------------------------------------
#define MT   128
#define KT   64
#define PSTR 68              // P smem row stride (conflict-free A frags)
#define HSTR 264             // H smem row stride (conflict-free B frags)
#define SMEM_FLOATS (MT * PSTR + KT * HSTR + N_NODES + MT)
#define SMEM_BYTES  (SMEM_FLOATS * 4)

__device__ __forceinline__ unsigned f2tf32(float x) {
    unsigned u;
    asm("cvt.rna.tf32.f32 %0, %1;" : "=r"(u) : "f"(x));
    return u;
}

__device__ __forceinline__ void mma_tf32(float* c, unsigned a0, unsigned a1,
                                         unsigned a2, unsigned a3,
                                         unsigned b0, unsigned b1) {
    asm volatile(
        "mma.sync.aligned.m16n8k8.row.col.f32.tf32.tf32.f32 "
        "{%0,%1,%2,%3}, {%4,%5,%6,%7}, {%8,%9}, {%0,%1,%2,%3};"
        : "+f"(c[0]), "+f"(c[1]), "+f"(c[2]), "+f"(c[3])
        : "r"(a0), "r"(a1), "r"(a2), "r"(a3), "r"(b0), "r"(b1));
}

__global__ void __launch_bounds__(512, 1) gat_fused(const int* __restrict__ adj,
                                                    float* __restrict__ out) {
    extern __shared__ float smem[];
    float* Ps  = smem;                    // [128][68]
    float* Hs  = Ps + MT * PSTR;          // [64][264]
    float* s2s = Hs + KT * HSTR;          // [8192]
    float* Zs  = s2s + N_NODES;           // [128]

    int tid = threadIdx.x;
    int rowBase = blockIdx.x * MT;

    // preload all of s2 into smem (32 KB, read 128x per CTA)
#pragma unroll
    for (int q = 0; q < 16; q++) s2s[q * 512 + tid] = g_s2[q * 512 + tid];

    // per-thread P-production mapping: row pr, 16 cols starting at pcg*16
    int pr = tid >> 2;
    int pcg = tid & 3;
    float s1r = g_s1[rowBase + pr];
    float tmax = s1r + g_s2max;
    float mr = tmax >= 0.f ? tmax : ALPHA * tmax;   // valid softmax shift
    float zacc = 0.f;
    const int* adjRow = adj + (size_t)(rowBase + pr) * N_NODES + pcg * 16;

    int warp = tid >> 5, lane = tid & 31;
    int wm = warp >> 2, wn = warp & 3;
    int lr = lane >> 2, lc = lane & 3;

    float c[2][8][4];
#pragma unroll
    for (int mt = 0; mt < 2; mt++)
#pragma unroll
        for (int nt = 0; nt < 8; nt++)
#pragma unroll
            for (int q = 0; q < 4; q++) c[mt][nt][q] = 0.f;

    __syncthreads();   // s2s ready

    for (int kc = 0; kc < N_NODES / KT; kc++) {
        int j0 = kc * KT;

        // ---- produce P tile [128 x 64] ----
        const int4* ap = (const int4*)(adjRow + j0);
        float* prow = Ps + pr * PSTR + pcg * 16;
#pragma unroll
        for (int q = 0; q < 4; q++) {
            int4 av = ap[q];
            int jb = j0 + pcg * 16 + q * 4;
            float p[4];
            int m[4] = {av.x, av.y, av.z, av.w};
#pragma unroll
            for (int l = 0; l < 4; l++) {
                float t = s1r + s2s[jb + l];
                float e = t >= 0.f ? t : ALPHA * t;
                float pv = (m[l] > 0) ? __expf(e - mr) : 0.f;
                zacc += pv;
                p[l] = __uint_as_float(f2tf32(pv));
            }
            *(float4*)(prow + q * 4) = make_float4(p[0], p[1], p[2], p[3]);
        }

        // ---- load H chunk [64 x 256] fp32 (L2 resident), tf32-round ----
        const float4* hp = (const float4*)(g_h + (size_t)j0 * FDIM);
#pragma unroll
        for (int q = 0; q < 8; q++) {
            float4 v = hp[q * 512 + tid];
            int idx = q * 2048 + tid * 4;
            int jr = idx >> 8, cc = idx & 255;
            v.x = __uint_as_float(f2tf32(v.x));
            v.y = __uint_as_float(f2tf32(v.y));
            v.z = __uint_as_float(f2tf32(v.z));
            v.w = __uint_as_float(f2tf32(v.w));
            *(float4*)&Hs[jr * HSTR + cc] = v;
        }
        __syncthreads();

        // ---- mma: 8 k-steps of m16n8k8 ----
#pragma unroll
        for (int k = 0; k < 8; k++) {
            unsigned b[8][2];
            int brow = k * 8 + lc;
            int bcol = wn * 64 + lr;
#pragma unroll
            for (int nt = 0; nt < 8; nt++) {
                b[nt][0] = __float_as_uint(Hs[brow * HSTR + bcol + nt * 8]);
                b[nt][1] = __float_as_uint(Hs[(brow + 4) * HSTR + bcol + nt * 8]);
            }
#pragma unroll
            for (int mt = 0; mt < 2; mt++) {
                int ar = wm * 32 + mt * 16 + lr;
                int ac = k * 8 + lc;
                unsigned a0 = __float_as_uint(Ps[ar * PSTR + ac]);
                unsigned a1 = __float_as_uint(Ps[(ar + 8) * PSTR + ac]);
                unsigned a2 = __float_as_uint(Ps[ar * PSTR + ac + 4]);
                unsigned a3 = __float_as_uint(Ps[(ar + 8) * PSTR + ac + 4]);
#pragma unroll
                for (int nt = 0; nt < 8; nt++)
                    mma_tf32(c[mt][nt], a0, a1, a2, a3, b[nt][0], b[nt][1]);
            }
        }
        __syncthreads();
    }

    // ---- Z reduce: 4 threads per row -> Zs[row] ----
    float z = zacc;
    z += __shfl_xor_sync(0xFFFFFFFFu, z, 1);
    z += __shfl_xor_sync(0xFFFFFFFFu, z, 2);
    if ((tid & 3) == 0) Zs[pr] = z;
    __syncthreads();

    // ---- epilogue: divide by Z, ELU, store ----
#pragma unroll
    for (int mt = 0; mt < 2; mt++) {
        int r0 = wm * 32 + mt * 16 + lr;
        float iz0 = 1.f / Zs[r0];
        float iz1 = 1.f / Zs[r0 + 8];
#pragma unroll
        for (int nt = 0; nt < 8; nt++) {
            int col = wn * 64 + nt * 8 + lc * 2;
            float v0 = c[mt][nt][0] * iz0;
            float v1 = c[mt][nt][1] * iz0;
            float v2 = c[mt][nt][2] * iz1;
            float v3 = c[mt][nt][3] * iz1;
            v0 = v0 > 0.f ? v0 : (__expf(v0) - 1.f);
            v1 = v1 > 0.f ? v1 : (__expf(v1) - 1.f);
            v2 = v2 > 0.f ? v2 : (__expf(v2) - 1.f);
            v3 = v3 > 0.f ? v3 : (__expf(v3) - 1.f);
            size_t o0 = (size_t)(rowBase + r0) * FDIM + col;
            size_t o1 = (size_t)(rowBase + r0 + 8) * FDIM + col;
            out[o0] = v0; out[o0 + 1] = v1;
            out[o1] = v2; out[o1 + 1] = v3;
        }
    }
}

// ---------------------------------------------------------------------------
extern "C" void kernel_launch(void* const* d_in, const int* in_sizes, int n_in,
                              void* d_out, int out_size) {
    const float* X   = (const float*)d_in[0];   // [8192,256]
    const int*   adj = (const int*)d_in[1];     // [8192,8192]
    const float* W   = (const float*)d_in[2];   // [256,256]
    const float* a   = (const float*)d_in[3];   // [512,1]
    float* out = (float*)d_out;                 // [8192,256]

    gemm_xw<<<dim3(FDIM / BN, N_NODES / BM), 256>>>(X, W);
    compute_s<<<N_NODES / 8, 256>>>(a);
    s2max_kernel<<<1, 1024>>>();

    cudaFuncSetAttribute(gat_fused, cudaFuncAttributeMaxDynamicSharedMemorySize,
                         SMEM_BYTES);
    gat_fused<<<N_NODES / MT, 512, SMEM_BYTES>>>(adj, out);
}

// round 7
// speedup vs baseline: 1.7384x; 1.7384x over previous
#include <cuda_runtime.h>
#include <cuda_bf16.h>
#include <math.h>
#include <stdint.h>

// ---------------------------------------------------------------------------
// GAT layer, N=8192, Fin=Fout=256.
//   h  = X @ W; s1 = h@a[:256]; s2 = h@a[256:]
//   e_ij = LeakyReLU(s1_i + s2_j), adj-masked row softmax, out = ELU(P @ h)
// Softmax shift: m_i = LR(s1_i + max(s2)) (LR monotone) -> adj read ONCE.
// ---------------------------------------------------------------------------

#define N_NODES 8192
#define FDIM    256
#define ALPHA   0.2f

__device__ float g_h[N_NODES * FDIM];     // 8 MB
__device__ float g_s1[N_NODES];
__device__ float g_s2[N_NODES];
__device__ float g_s2max;

// ---------------------------------------------------------------------------
// K1: h = X @ W
// ---------------------------------------------------------------------------
#define BM 64
#define BN 64
#define BK 16

__global__ void __launch_bounds__(256) gemm_xw(const float* __restrict__ X,
                                               const float* __restrict__ W) {
    __shared__ float As[BK][BM + 4];
    __shared__ float Bs[BK][BN + 4];
    int tid = threadIdx.x;
    int m0 = blockIdx.y * BM;
    int n0 = blockIdx.x * BN;
    int tx = tid & 15, ty = tid >> 4;

    float acc[4][4];
#pragma unroll
    for (int i = 0; i < 4; i++)
#pragma unroll
        for (int j = 0; j < 4; j++) acc[i][j] = 0.f;

    for (int kt = 0; kt < FDIM; kt += BK) {
        {
            int r = tid >> 2, k4 = (tid & 3) * 4;
            float4 v = *(const float4*)(X + (size_t)(m0 + r) * FDIM + kt + k4);
            As[k4 + 0][r] = v.x; As[k4 + 1][r] = v.y;
            As[k4 + 2][r] = v.z; As[k4 + 3][r] = v.w;
        }
        {
            int r = tid >> 4, c4 = (tid & 15) * 4;
            *(float4*)&Bs[r][c4] = *(const float4*)(W + (size_t)(kt + r) * FDIM + n0 + c4);
        }
        __syncthreads();
#pragma unroll
        for (int k = 0; k < BK; k++) {
            float4 a4 = *(const float4*)&As[k][ty * 4];
            float4 b4 = *(const float4*)&Bs[k][tx * 4];
            float a[4] = {a4.x, a4.y, a4.z, a4.w};
            float b[4] = {b4.x, b4.y, b4.z, b4.w};
#pragma unroll
            for (int i = 0; i < 4; i++)
#pragma unroll
                for (int j = 0; j < 4; j++) acc[i][j] = fmaf(a[i], b[j], acc[i][j]);
        }
        __syncthreads();
    }
#pragma unroll
    for (int i = 0; i < 4; i++)
#pragma unroll
        for (int j = 0; j < 4; j++)
            g_h[(size_t)(m0 + ty * 4 + i) * FDIM + n0 + tx * 4 + j] = acc[i][j];
}

// ---------------------------------------------------------------------------
// K2: s1/s2 row dots (one warp per row)
// ---------------------------------------------------------------------------
__global__ void __launch_bounds__(256) compute_s(const float* __restrict__ a) {
    int warp = threadIdx.x >> 5;
    int lane = threadIdx.x & 31;
    int row = blockIdx.x * 8 + warp;
    const float* hr = g_h + (size_t)row * FDIM;
    float d1 = 0.f, d2 = 0.f;
#pragma unroll
    for (int q = 0; q < 2; q++) {
        int c = lane * 4 + q * 128;
        float4 h4 = *(const float4*)(hr + c);
        float4 a1 = *(const float4*)(a + c);
        float4 a2 = *(const float4*)(a + FDIM + c);
        d1 += h4.x * a1.x + h4.y * a1.y + h4.z * a1.z + h4.w * a1.w;
        d2 += h4.x * a2.x + h4.y * a2.y + h4.z * a2.z + h4.w * a2.w;
    }
#pragma unroll
    for (int off = 16; off > 0; off >>= 1) {
        d1 += __shfl_xor_sync(0xFFFFFFFFu, d1, off);
        d2 += __shfl_xor_sync(0xFFFFFFFFu, d2, off);
    }
    if (lane == 0) { g_s1[row] = d1; g_s2[row] = d2; }
}

// ---------------------------------------------------------------------------
// K3: global max of s2
// ---------------------------------------------------------------------------
__global__ void __launch_bounds__(1024) s2max_kernel() {
    __shared__ float sm[1024];
    float m = -INFINITY;
    for (int i = threadIdx.x; i < N_NODES; i += 1024) m = fmaxf(m, g_s2[i]);
    sm[threadIdx.x] = m;
    __syncthreads();
    for (int s = 512; s > 0; s >>= 1) {
        if (threadIdx.x < s) sm[threadIdx.x] = fmaxf(sm[threadIdx.x], sm[threadIdx.x + s]);
        __syncthreads();
    }
    if (threadIdx.x == 0) g_s2max = sm[0];
}

// ---------------------------------------------------------------------------
// K4: fused masked-softmax @ h, tf32 mma.sync, ELU.
//   MT=64 rows/CTA -> grid=128 (2x prev). 512 thr = 16 warps as 2(m) x 8(n);
//   each warp: 2 m16 tiles x 4 n8 tiles, k-chunks of 64 (8 mma k-steps).
//   Register-staged prefetch of next chunk's adj + H overlaps the mma loop.
// ---------------------------------------------------------------------------
#define MT   64
#define KT   64
#define NCHUNK (N_NODES / KT)
#define PSTR 68
#define HSTR 264
#define SMEM_FLOATS (MT * PSTR + KT * HSTR + N_NODES + MT)
#define SMEM_BYTES  (SMEM_FLOATS * 4)

__device__ __forceinline__ unsigned f2tf32(float x) {
    unsigned u;
    asm("cvt.rna.tf32.f32 %0, %1;" : "=r"(u) : "f"(x));
    return u;
}

__device__ __forceinline__ void mma_tf32(float* c, unsigned a0, unsigned a1,
                                         unsigned a2, unsigned a3,
                                         unsigned b0, unsigned b1) {
    asm volatile(
        "mma.sync.aligned.m16n8k8.row.col.f32.tf32.tf32.f32 "
        "{%0,%1,%2,%3}, {%4,%5,%6,%7}, {%8,%9}, {%0,%1,%2,%3};"
        : "+f"(c[0]), "+f"(c[1]), "+f"(c[2]), "+f"(c[3])
        : "r"(a0), "r"(a1), "r"(a2), "r"(a3), "r"(b0), "r"(b1));
}

__global__ void __launch_bounds__(512, 1) gat_fused(const int* __restrict__ adj,
                                                    float* __restrict__ out) {
    extern __shared__ float smem[];
    float* Ps  = smem;                    // [64][68]
    float* Hs  = Ps + MT * PSTR;          // [64][264]
    float* s2s = Hs + KT * HSTR;          // [8192]
    float* Zs  = s2s + N_NODES;           // [64]

    int tid = threadIdx.x;
    int rowBase = blockIdx.x * MT;

    // preload all of s2 (32 KB; reused 64x per CTA)
#pragma unroll
    for (int q = 0; q < 16; q++) s2s[q * 512 + tid] = g_s2[q * 512 + tid];

    // P-production mapping: row pr (8 threads/row), cols pcg*8..+8
    int pr = tid >> 3;
    int pcg = tid & 7;
    float s1r = g_s1[rowBase + pr];
    float tmax = s1r + g_s2max;
    float mr = tmax >= 0.f ? tmax : ALPHA * tmax;   // valid softmax shift
    float zacc = 0.f;
    const int4* adjRow = (const int4*)(adj + (size_t)(rowBase + pr) * N_NODES);

    int warp = tid >> 5, lane = tid & 31;
    int wm = warp >> 3, wn = warp & 7;
    int lr = lane >> 2, lc = lane & 3;

    float c[2][4][4];
#pragma unroll
    for (int mt = 0; mt < 2; mt++)
#pragma unroll
        for (int nt = 0; nt < 4; nt++)
#pragma unroll
            for (int q = 0; q < 4; q++) c[mt][nt][q] = 0.f;

    // ---- prefetch chunk 0 into registers ----
    int4 aReg[2];
    float4 hReg[8];
#pragma unroll
    for (int q = 0; q < 2; q++) aReg[q] = adjRow[pcg * 2 + q];
    {
        const float4* hp = (const float4*)g_h;
#pragma unroll
        for (int q = 0; q < 8; q++) hReg[q] = hp[q * 512 + tid];
    }

    __syncthreads();   // s2s ready

    for (int kc = 0; kc < NCHUNK; kc++) {
        int j0 = kc * KT;

        // ---- P tile from prefetched adj regs ----
        float* prow = Ps + pr * PSTR + pcg * 8;
#pragma unroll
        for (int q = 0; q < 2; q++) {
            int4 av = aReg[q];
            int jb = j0 + pcg * 8 + q * 4;
            float4 s2v = *(const float4*)(s2s + jb);
            float sv[4] = {s2v.x, s2v.y, s2v.z, s2v.w};
            int m[4] = {av.x, av.y, av.z, av.w};
            float p[4];
#pragma unroll
            for (int l = 0; l < 4; l++) {
                float t = s1r + sv[l];
                float e = t >= 0.f ? t : ALPHA * t;
                float pv = (m[l] > 0) ? __expf(e - mr) : 0.f;
                zacc += pv;
                p[l] = __uint_as_float(f2tf32(pv));
            }
            *(float4*)(prow + q * 4) = make_float4(p[0], p[1], p[2], p[3]);
        }

        // ---- H tile from prefetched regs (tf32-round on store) ----
#pragma unroll
        for (int q = 0; q < 8; q++) {
            float4 v = hReg[q];
            int idx = q * 2048 + tid * 4;
            int jr = idx >> 8, cc = idx & 255;
            v.x = __uint_as_float(f2tf32(v.x));
            v.y = __uint_as_float(f2tf32(v.y));
            v.z = __uint_as_float(f2tf32(v.z));
            v.w = __uint_as_float(f2tf32(v.w));
            *(float4*)&Hs[jr * HSTR + cc] = v;
        }
        __syncthreads();

        // ---- prefetch chunk kc+1 (latency hides behind mma below) ----
        int jn = (kc + 1 < NCHUNK) ? j0 + KT : 0;
#pragma unroll
        for (int q = 0; q < 2; q++) aReg[q] = adjRow[jn / 4 + pcg * 2 + q];
        {
            const float4* hp = (const float4*)(g_h + (size_t)jn * FDIM);
#pragma unroll
            for (int q = 0; q < 8; q++) hReg[q] = hp[q * 512 + tid];
        }

        // ---- mma: 8 k-steps of m16n8k8 ----
#pragma unroll
        for (int k = 0; k < 8; k++) {
            unsigned b[4][2];
            int brow = k * 8 + lc;
            int bcol = wn * 32 + lr;
#pragma unroll
            for (int nt = 0; nt < 4; nt++) {
                b[nt][0] = __float_as_uint(Hs[brow * HSTR + bcol + nt * 8]);
                b[nt][1] = __float_as_uint(Hs[(brow + 4) * HSTR + bcol + nt * 8]);
            }
#pragma unroll
            for (int mt = 0; mt < 2; mt++) {
                int ar = wm * 32 + mt * 16 + lr;
                int ac = k * 8 + lc;
                unsigned a0 = __float_as_uint(Ps[ar * PSTR + ac]);
                unsigned a1 = __float_as_uint(Ps[(ar + 8) * PSTR + ac]);
                unsigned a2 = __float_as_uint(Ps[ar * PSTR + ac + 4]);
                unsigned a3 = __float_as_uint(Ps[(ar + 8) * PSTR + ac + 4]);
#pragma unroll
                for (int nt = 0; nt < 4; nt++)
                    mma_tf32(c[mt][nt], a0, a1, a2, a3, b[nt][0], b[nt][1]);
            }
        }
        __syncthreads();
    }

    // ---- Z reduce: 8 threads per row ----
    float z = zacc;
    z += __shfl_xor_sync(0xFFFFFFFFu, z, 1);
    z += __shfl_xor_sync(0xFFFFFFFFu, z, 2);
    z += __shfl_xor_sync(0xFFFFFFFFu, z, 4);
    if ((tid & 7) == 0) Zs[pr] = z;
    __syncthreads();

    // ---- epilogue: /Z, ELU, store ----
#pragma unroll
    for (int mt = 0; mt < 2; mt++) {
        int r0 = wm * 32 + mt * 16 + lr;
        float iz0 = 1.f / Zs[r0];
        float iz1 = 1.f / Zs[r0 + 8];
#pragma unroll
        for (int nt = 0; nt < 4; nt++) {
            int col = wn * 32 + nt * 8 + lc * 2;
            float v0 = c[mt][nt][0] * iz0;
            float v1 = c[mt][nt][1] * iz0;
            float v2 = c[mt][nt][2] * iz1;
            float v3 = c[mt][nt][3] * iz1;
            v0 = v0 > 0.f ? v0 : (__expf(v0) - 1.f);
            v1 = v1 > 0.f ? v1 : (__expf(v1) - 1.f);
            v2 = v2 > 0.f ? v2 : (__expf(v2) - 1.f);
            v3 = v3 > 0.f ? v3 : (__expf(v3) - 1.f);
            size_t o0 = (size_t)(rowBase + r0) * FDIM + col;
            size_t o1 = (size_t)(rowBase + r0 + 8) * FDIM + col;
            out[o0] = v0; out[o0 + 1] = v1;
            out[o1] = v2; out[o1 + 1] = v3;
        }
    }
}

// ---------------------------------------------------------------------------
extern "C" void kernel_launch(void* const* d_in, const int* in_sizes, int n_in,
                              void* d_out, int out_size) {
    const float* X   = (const float*)d_in[0];   // [8192,256]
    const int*   adj = (const int*)d_in[1];     // [8192,8192]
    const float* W   = (const float*)d_in[2];   // [256,256]
    const float* a   = (const float*)d_in[3];   // [512,1]
    float* out = (float*)d_out;                 // [8192,256]

    gemm_xw<<<dim3(FDIM / BN, N_NODES / BM), 256>>>(X, W);
    compute_s<<<N_NODES / 8, 256>>>(a);
    s2max_kernel<<<1, 1024>>>();

    cudaFuncSetAttribute(gat_fused, cudaFuncAttributeMaxDynamicSharedMemorySize,
                         SMEM_BYTES);
    gat_fused<<<N_NODES / MT, 512, SMEM_BYTES>>>(adj, out);
}

// round 8
// speedup vs baseline: 2.7405x; 1.5765x over previous
#include <cuda_runtime.h>
#include <cuda_bf16.h>
#include <cuda_fp16.h>
#include <math.h>
#include <stdint.h>

// ---------------------------------------------------------------------------
// GAT layer, N=8192, Fin=Fout=256.
//   h  = X @ W; s1 = h@a[:256]; s2 = h@a[256:]
//   e_ij = LeakyReLU(s1_i + s2_j), adj-masked row softmax, out = ELU(P @ h)
// Softmax shift: m_i = LR(s1_i + max(s2)) (LR monotone) -> adj read ONCE.
// PV GEMM in fp16 (same 10-bit mantissa as tf32), fp32 accum.
// ---------------------------------------------------------------------------

#define N_NODES 8192
#define FDIM    256
#define ALPHA   0.2f

__device__ float  g_h [N_NODES * FDIM];   // 8 MB fp32 (for s1/s2)
__device__ __half g_hh[N_NODES * FDIM];   // 4 MB half (for PV mma)
__device__ float  g_s1[N_NODES];
__device__ float  g_s2[N_NODES];
__device__ float  g_s2max;

// ---------------------------------------------------------------------------
// K1: h = X @ W
// ---------------------------------------------------------------------------
#define BM 64
#define BN 64
#define BK 16

__global__ void __launch_bounds__(256) gemm_xw(const float* __restrict__ X,
                                               const float* __restrict__ W) {
    __shared__ float As[BK][BM + 4];
    __shared__ float Bs[BK][BN + 4];
    int tid = threadIdx.x;
    int m0 = blockIdx.y * BM;
    int n0 = blockIdx.x * BN;
    int tx = tid & 15, ty = tid >> 4;

    float acc[4][4];
#pragma unroll
    for (int i = 0; i < 4; i++)
#pragma unroll
        for (int j = 0; j < 4; j++) acc[i][j] = 0.f;

    for (int kt = 0; kt < FDIM; kt += BK) {
        {
            int r = tid >> 2, k4 = (tid & 3) * 4;
            float4 v = *(const float4*)(X + (size_t)(m0 + r) * FDIM + kt + k4);
            As[k4 + 0][r] = v.x; As[k4 + 1][r] = v.y;
            As[k4 + 2][r] = v.z; As[k4 + 3][r] = v.w;
        }
        {
            int r = tid >> 4, c4 = (tid & 15) * 4;
            *(float4*)&Bs[r][c4] = *(const float4*)(W + (size_t)(kt + r) * FDIM + n0 + c4);
        }
        __syncthreads();
#pragma unroll
        for (int k = 0; k < BK; k++) {
            float4 a4 = *(const float4*)&As[k][ty * 4];
            float4 b4 = *(const float4*)&Bs[k][tx * 4];
            float a[4] = {a4.x, a4.y, a4.z, a4.w};
            float b[4] = {b4.x, b4.y, b4.z, b4.w};
#pragma unroll
            for (int i = 0; i < 4; i++)
#pragma unroll
                for (int j = 0; j < 4; j++) acc[i][j] = fmaf(a[i], b[j], acc[i][j]);
        }
        __syncthreads();
    }
#pragma unroll
    for (int i = 0; i < 4; i++)
#pragma unroll
        for (int j = 0; j < 4; j++) {
            size_t idx = (size_t)(m0 + ty * 4 + i) * FDIM + n0 + tx * 4 + j;
            float v = acc[i][j];
            g_h[idx]  = v;
            g_hh[idx] = __float2half(v);
        }
}

// ---------------------------------------------------------------------------
// K2: s1/s2 row dots (one warp per row)
// ---------------------------------------------------------------------------
__global__ void __launch_bounds__(256) compute_s(const float* __restrict__ a) {
    int warp = threadIdx.x >> 5;
    int lane = threadIdx.x & 31;
    int row = blockIdx.x * 8 + warp;
    const float* hr = g_h + (size_t)row * FDIM;
    float d1 = 0.f, d2 = 0.f;
#pragma unroll
    for (int q = 0; q < 2; q++) {
        int c = lane * 4 + q * 128;
        float4 h4 = *(const float4*)(hr + c);
        float4 a1 = *(const float4*)(a + c);
        float4 a2 = *(const float4*)(a + FDIM + c);
        d1 += h4.x * a1.x + h4.y * a1.y + h4.z * a1.z + h4.w * a1.w;
        d2 += h4.x * a2.x + h4.y * a2.y + h4.z * a2.z + h4.w * a2.w;
    }
#pragma unroll
    for (int off = 16; off > 0; off >>= 1) {
        d1 += __shfl_xor_sync(0xFFFFFFFFu, d1, off);
        d2 += __shfl_xor_sync(0xFFFFFFFFu, d2, off);
    }
    if (lane == 0) { g_s1[row] = d1; g_s2[row] = d2; }
}

// ---------------------------------------------------------------------------
// K3: global max of s2
// ---------------------------------------------------------------------------
__global__ void __launch_bounds__(1024) s2max_kernel() {
    __shared__ float sm[1024];
    float m = -INFINITY;
    for (int i = threadIdx.x; i < N_NODES; i += 1024) m = fmaxf(m, g_s2[i]);
    sm[threadIdx.x] = m;
    __syncthreads();
    for (int s = 512; s > 0; s >>= 1) {
        if (threadIdx.x < s) sm[threadIdx.x] = fmaxf(sm[threadIdx.x], sm[threadIdx.x + s]);
        __syncthreads();
    }
    if (threadIdx.x == 0) g_s2max = sm[0];
}

// ---------------------------------------------------------------------------
// K4: fused masked-softmax @ h, fp16 m16n8k16 mma + ldmatrix, ELU.
//   MT=64 rows/CTA, grid=128, 512 thr = 16 warps (2 m x 8 n).
//   Per warp: 2 m16 x 4 n8 tiles, 4 k16-steps per 64-chunk.
// ---------------------------------------------------------------------------
#define MT   64
#define KT   64
#define NCHUNK (N_NODES / KT)
#define PSTR 72       // halves; 144 B ≡ 16 mod 128 -> conflict-free ldmatrix
#define HSTR 264      // halves; 528 B ≡ 16 mod 128 -> conflict-free ldmatrix
#define PS_BYTES (MT * PSTR * 2)          // 9216
#define HS_BYTES (KT * HSTR * 2)          // 33792
#define SMEM_BYTES (PS_BYTES + HS_BYTES + N_NODES * 4 + MT * 4)  // 76032

__device__ __forceinline__ unsigned packh2(float a, float b) {
    __half2 h = __floats2half2_rn(a, b);
    return *(unsigned*)&h;
}

__device__ __forceinline__ void ldsm_x4(unsigned& r0, unsigned& r1,
                                        unsigned& r2, unsigned& r3, unsigned addr) {
    asm volatile("ldmatrix.sync.aligned.m8n8.x4.shared.b16 {%0,%1,%2,%3}, [%4];"
                 : "=r"(r0), "=r"(r1), "=r"(r2), "=r"(r3) : "r"(addr));
}

__device__ __forceinline__ void ldsm_x4_t(unsigned& r0, unsigned& r1,
                                          unsigned& r2, unsigned& r3, unsigned addr) {
    asm volatile("ldmatrix.sync.aligned.m8n8.x4.trans.shared.b16 {%0,%1,%2,%3}, [%4];"
                 : "=r"(r0), "=r"(r1), "=r"(r2), "=r"(r3) : "r"(addr));
}

__device__ __forceinline__ void mma_f16(float* c, unsigned a0, unsigned a1,
                                        unsigned a2, unsigned a3,
                                        unsigned b0, unsigned b1) {
    asm volatile(
        "mma.sync.aligned.m16n8k16.row.col.f32.f16.f16.f32 "
        "{%0,%1,%2,%3}, {%4,%5,%6,%7}, {%8,%9}, {%0,%1,%2,%3};"
        : "+f"(c[0]), "+f"(c[1]), "+f"(c[2]), "+f"(c[3])
        : "r"(a0), "r"(a1), "r"(a2), "r"(a3), "r"(b0), "r"(b1));
}

__global__ void __launch_bounds__(512, 1) gat_fused(const int* __restrict__ adj,
                                                    float* __restrict__ out) {
    extern __shared__ char smem[];
    __half* Ps  = (__half*)smem;                            // [64][72] halves
    __half* Hs  = (__half*)(smem + PS_BYTES);               // [64][264] halves
    float*  s2s = (float*)(smem + PS_BYTES + HS_BYTES);     // [8192]
    float*  Zs  = s2s + N_NODES;                            // [64]

    int tid = threadIdx.x;
    int rowBase = blockIdx.x * MT;

    // preload all of s2 (reused 64x per CTA)
#pragma unroll
    for (int q = 0; q < 16; q++) s2s[q * 512 + tid] = g_s2[q * 512 + tid];

    // P-production mapping: row pr (8 threads/row), cols pcg*8..+8
    int pr = tid >> 3;
    int pcg = tid & 7;
    float s1r = g_s1[rowBase + pr];
    float tmax = s1r + g_s2max;
    float mr = tmax >= 0.f ? tmax : ALPHA * tmax;   // valid softmax shift
    float zacc = 0.f;
    const int4* adjRow = (const int4*)(adj + (size_t)(rowBase + pr) * N_NODES);

    int warp = tid >> 5, lane = tid & 31;
    int wm = warp >> 3, wn = warp & 7;
    int lr = lane >> 2, lc = lane & 3;

    // ldmatrix base addresses (shared-space)
    unsigned psBase = (unsigned)__cvta_generic_to_shared(Ps);
    unsigned hsBase = (unsigned)__cvta_generic_to_shared(Hs);
    int lg = lane & 15, lh = (lane >> 4) << 3;   // row-in-group, 8-col select
    unsigned aAddr[2];
#pragma unroll
    for (int mt = 0; mt < 2; mt++)
        aAddr[mt] = psBase + ((wm * 32 + mt * 16 + lg) * PSTR + lh) * 2;
    unsigned bAddr[2];
#pragma unroll
    for (int ntp = 0; ntp < 2; ntp++)
        bAddr[ntp] = hsBase + (lg * HSTR + wn * 32 + ntp * 16 + lh) * 2;

    float c[2][4][4];
#pragma unroll
    for (int mt = 0; mt < 2; mt++)
#pragma unroll
        for (int nt = 0; nt < 4; nt++)
#pragma unroll
            for (int q = 0; q < 4; q++) c[mt][nt][q] = 0.f;

    // ---- prefetch chunk 0 ----
    int4 aReg[2];
    uint4 hReg[4];
#pragma unroll
    for (int q = 0; q < 2; q++) aReg[q] = adjRow[pcg * 2 + q];
    {
        const uint4* hp = (const uint4*)g_hh;
#pragma unroll
        for (int q = 0; q < 4; q++) hReg[q] = hp[q * 512 + tid];
    }

    __syncthreads();   // s2s ready

    for (int kc = 0; kc < NCHUNK; kc++) {
        int j0 = kc * KT;

        // ---- P tile (fp16) from prefetched adj regs ----
        {
            float p[8];
#pragma unroll
            for (int q = 0; q < 2; q++) {
                int4 av = aReg[q];
                int jb = j0 + pcg * 8 + q * 4;
                float4 s2v = *(const float4*)(s2s + jb);
                float sv[4] = {s2v.x, s2v.y, s2v.z, s2v.w};
                int m[4] = {av.x, av.y, av.z, av.w};
#pragma unroll
                for (int l = 0; l < 4; l++) {
                    float t = s1r + sv[l];
                    float e = t >= 0.f ? t : ALPHA * t;
                    float pv = (m[l] > 0) ? __expf(e - mr) : 0.f;
                    zacc += pv;
                    p[q * 4 + l] = pv;
                }
            }
            uint4 pk;
            pk.x = packh2(p[0], p[1]); pk.y = packh2(p[2], p[3]);
            pk.z = packh2(p[4], p[5]); pk.w = packh2(p[6], p[7]);
            *(uint4*)(Ps + pr * PSTR + pcg * 8) = pk;
        }

        // ---- H tile (half) from prefetched regs ----
        // hReg[q] = uint4 #(q*512+tid) of chunk; row=(q*512+tid)>>5, col=(tid&31)*8
#pragma unroll
        for (int q = 0; q < 4; q++) {
            int jr = (q * 512 + tid) >> 5;
            int cch = (tid & 31) * 8;
            *(uint4*)(Hs + jr * HSTR + cch) = hReg[q];
        }
        __syncthreads();

        // ---- prefetch chunk kc+1 (hides behind mma) ----
        int jn = (kc + 1 < NCHUNK) ? j0 + KT : 0;
#pragma unroll
        for (int q = 0; q < 2; q++) aReg[q] = adjRow[jn / 4 + pcg * 2 + q];
        {
            const uint4* hp = (const uint4*)(g_hh + (size_t)jn * FDIM);
#pragma unroll
            for (int q = 0; q < 4; q++) hReg[q] = hp[q * 512 + tid];
        }

        // ---- mma: 4 k16-steps ----
#pragma unroll
        for (int k = 0; k < 4; k++) {
            unsigned b[2][4];
#pragma unroll
            for (int ntp = 0; ntp < 2; ntp++)
                ldsm_x4_t(b[ntp][0], b[ntp][1], b[ntp][2], b[ntp][3],
                          bAddr[ntp] + k * 16 * HSTR * 2);
#pragma unroll
            for (int mt = 0; mt < 2; mt++) {
                unsigned a0, a1, a2, a3;
                ldsm_x4(a0, a1, a2, a3, aAddr[mt] + k * 32);
#pragma unroll
                for (int ntp = 0; ntp < 2; ntp++) {
                    mma_f16(c[mt][ntp * 2 + 0], a0, a1, a2, a3, b[ntp][0], b[ntp][1]);
                    mma_f16(c[mt][ntp * 2 + 1], a0, a1, a2, a3, b[ntp][2], b[ntp][3]);
                }
            }
        }
        __syncthreads();
    }

    // ---- Z reduce: 8 threads per row ----
    float z = zacc;
    z += __shfl_xor_sync(0xFFFFFFFFu, z, 1);
    z += __shfl_xor_sync(0xFFFFFFFFu, z, 2);
    z += __shfl_xor_sync(0xFFFFFFFFu, z, 4);
    if ((tid & 7) == 0) Zs[pr] = z;
    __syncthreads();

    // ---- epilogue: /Z, ELU, store ----
#pragma unroll
    for (int mt = 0; mt < 2; mt++) {
        int r0 = wm * 32 + mt * 16 + lr;
        float iz0 = 1.f / Zs[r0];
        float iz1 = 1.f / Zs[r0 + 8];
#pragma unroll
        for (int nt = 0; nt < 4; nt++) {
            int col = wn * 32 + nt * 8 + lc * 2;
            float v0 = c[mt][nt][0] * iz0;
            float v1 = c[mt][nt][1] * iz0;
            float v2 = c[mt][nt][2] * iz1;
            float v3 = c[mt][nt][3] * iz1;
            v0 = v0 > 0.f ? v0 : (__expf(v0) - 1.f);
            v1 = v1 > 0.f ? v1 : (__expf(v1) - 1.f);
            v2 = v2 > 0.f ? v2 : (__expf(v2) - 1.f);
            v3 = v3 > 0.f ? v3 : (__expf(v3) - 1.f);
            size_t o0 = (size_t)(rowBase + r0) * FDIM + col;
            size_t o1 = (size_t)(rowBase + r0 + 8) * FDIM + col;
            out[o0] = v0; out[o0 + 1] = v1;
            out[o1] = v2; out[o1 + 1] = v3;
        }
    }
}

// ---------------------------------------------------------------------------
extern "C" void kernel_launch(void* const* d_in, const int* in_sizes, int n_in,
                              void* d_out, int out_size) {
    const float* X   = (const float*)d_in[0];   // [8192,256]
    const int*   adj = (const int*)d_in[1];     // [8192,8192]
    const float* W   = (const float*)d_in[2];   // [256,256]
    const float* a   = (const float*)d_in[3];   // [512,1]
    float* out = (float*)d_out;                 // [8192,256]

    gemm_xw<<<dim3(FDIM / BN, N_NODES / BM), 256>>>(X, W);
    compute_s<<<N_NODES / 8, 256>>>(a);
    s2max_kernel<<<1, 1024>>>();

    cudaFuncSetAttribute(gat_fused, cudaFuncAttributeMaxDynamicSharedMemorySize,
                         SMEM_BYTES);
    gat_fused<<<N_NODES / MT, 512, SMEM_BYTES>>>(adj, out);
}